// round 1
// baseline (speedup 1.0000x reference)
#include <cuda_runtime.h>
#include <cuda_bf16.h>

#define PH    16
#define PW    16
#define NM    16      // number of DCT bases
#define HDIM  224
#define WDIM  224
#define CDIM  64
#define BDIM  16
#define HW    (HDIM * WDIM)

// One CTA per (b, patch_h, patch_w) 16x16 patch. 256 threads.
// Phase 1: channel mean (64 channels), fully float4-coalesced.
// Phase 2: 16 DCT coefficients via per-warp shuffle reductions.
// Phase 3: broadcast each coefficient over its 16x16 footprint, float4 stores.
__global__ __launch_bounds__(256, 8)
void msp_dct_kernel(const float* __restrict__ x,
                    const float* __restrict__ bases,
                    float* __restrict__ out) {
    __shared__ float4 sPart[256];            // 4 KB  partial channel sums
    __shared__ float  sMean[256];            // 1 KB  mean patch (i*16 + j)
    __shared__ float  sBase[NM * 256];       // 16 KB dct bases
    __shared__ float  sCoef[NM];             // coefficients

    const int t  = threadIdx.x;
    const int pw = blockIdx.x;               // 0..13
    const int ph = blockIdx.y;               // 0..13
    const int b  = blockIdx.z;               // 0..15
    const int h0 = ph * PH;
    const int w0 = pw * PW;

    // ---- load bases into smem (4096 floats = 1024 float4) ----
    {
        const float4* bsrc = reinterpret_cast<const float4*>(bases);
        float4*       bdst = reinterpret_cast<float4*>(sBase);
        #pragma unroll
        for (int k = 0; k < 4; k++) bdst[t + k * 256] = bsrc[t + k * 256];
    }

    // ---- phase 1: mean over C=64 ----
    // thread -> pixel-quad g (0..63) and channel-slice (0..3, 16 channels each)
    const int g   = t & 63;
    const int pi  = g >> 2;                  // row within patch 0..15
    const int pj4 = (g & 3) * 4;             // col quad start 0,4,8,12
    const int csl = t >> 6;                  // channel slice 0..3
    {
        const float* p = x + ((size_t)(b * CDIM + csl * 16)) * HW
                           + (size_t)(h0 + pi) * WDIM + (w0 + pj4);
        float4 acc = make_float4(0.f, 0.f, 0.f, 0.f);
        #pragma unroll
        for (int cc = 0; cc < 16; cc++) {
            const float4 v = *reinterpret_cast<const float4*>(p);
            acc.x += v.x; acc.y += v.y; acc.z += v.z; acc.w += v.w;
            p += HW;
        }
        sPart[t] = acc;
    }
    __syncthreads();

    if (t < 64) {
        const float4 a0 = sPart[t];
        const float4 a1 = sPart[t + 64];
        const float4 a2 = sPart[t + 128];
        const float4 a3 = sPart[t + 192];
        const float  s  = 1.0f / (float)CDIM;
        const int base = pi * 16 + pj4;      // pi,pj4 valid since t<64 -> g==t
        sMean[base + 0] = (a0.x + a1.x + a2.x + a3.x) * s;
        sMean[base + 1] = (a0.y + a1.y + a2.y + a3.y) * s;
        sMean[base + 2] = (a0.z + a1.z + a2.z + a3.z) * s;
        sMean[base + 3] = (a0.w + a1.w + a2.w + a3.w) * s;
    }
    __syncthreads();

    // ---- phase 2: 16 coefficients, 2 per warp ----
    const int warp = t >> 5;
    const int lane = t & 31;
    #pragma unroll
    for (int mm = 0; mm < 2; mm++) {
        const int m = warp * 2 + mm;
        float a = 0.f;
        #pragma unroll
        for (int r = 0; r < 8; r++) {
            const int p = lane + r * 32;
            a += sMean[p] * sBase[m * 256 + p];
        }
        #pragma unroll
        for (int off = 16; off; off >>= 1)
            a += __shfl_xor_sync(0xffffffffu, a, off);
        if (lane == 0) sCoef[m] = a;
    }
    __syncthreads();

    // ---- phase 3: broadcast writes, 4 float4 stores per thread ----
    #pragma unroll
    for (int k = 0; k < 4; k++) {
        const int idx = t + k * 256;         // 0..1023
        const int m   = idx >> 6;            // base index (warp-uniform)
        const int gg  = idx & 63;
        const int ii  = gg >> 2;
        const int jj  = (gg & 3) * 4;
        const float v = sCoef[m];
        const float4 vv = make_float4(v, v, v, v);
        float* o = out + ((size_t)(b * NM + m) * HDIM + (h0 + ii)) * WDIM
                       + (w0 + jj);
        *reinterpret_cast<float4*>(o) = vv;
    }
}

extern "C" void kernel_launch(void* const* d_in, const int* in_sizes, int n_in,
                              void* d_out, int out_size) {
    const float* x     = (const float*)d_in[0];
    const float* bases = (const float*)d_in[1];
    float*       out   = (float*)d_out;
    dim3 grid(WDIM / PW, HDIM / PH, BDIM);   // 14 x 14 x 16 = 3136 CTAs
    msp_dct_kernel<<<grid, 256>>>(x, bases, out);
}